// round 12
// baseline (speedup 1.0000x reference)
#include <cuda_runtime.h>
#include <cuda_fp16.h>
#include <cstdint>

#define B_ 8
#define D_ 128
#define N_ 2048
#define BM 128
#define BN 128
#define NITER (N_ / BN)

__device__ __align__(16) __half g_Qh[B_ * D_ * N_];  // [b][d][n]
__device__ __align__(16) __half g_Kh[B_ * D_ * N_];  // [b][d][m]
__device__ __align__(16) __half g_Vh[B_ * D_ * N_];  // [b][v][n]

__device__ __forceinline__ uint32_t s2u(const void* p) {
    uint32_t a;
    asm("{ .reg .u64 t; cvta.to.shared.u64 t, %1; cvt.u32.u64 %0, t; }" : "=r"(a) : "l"(p));
    return a;
}

#define CPA16(dst, src) \
    asm volatile("cp.async.cg.shared.global [%0], [%1], 16;" :: "r"(dst), "l"(src))
#define CPA_COMMIT() asm volatile("cp.async.commit_group;" ::: "memory")
#define CPA_WAIT0()  asm volatile("cp.async.wait_group 0;" ::: "memory")

#define MBAR_INIT(a, c) asm volatile("mbarrier.init.shared.b64 [%0], %1;" :: "r"(a), "r"(c) : "memory")
#define MBAR_ARRIVE(a)  asm volatile("mbarrier.arrive.shared.b64 _, [%0];" :: "r"(a) : "memory")
#define MBAR_WAIT(a, ph) do {                                                            \
    uint32_t _m = (a); uint32_t _p = (ph); uint32_t _d;                                  \
    asm volatile("{ .reg .pred p;"                                                      \
        " mbarrier.try_wait.parity.shared.b64 p, [%1], %2;"                             \
        " selp.b32 %0, 1, 0, p; }" : "=r"(_d) : "r"(_m), "r"(_p) : "memory");           \
    if (!_d) {                                                                           \
        asm volatile("{ .reg .pred P1; WL_%=:"                                          \
        " mbarrier.try_wait.parity.shared.b64 P1, [%0], %1;"                            \
        " @P1 bra.uni WD_%=; bra.uni WL_%=; WD_%=: }" :: "r"(_m), "r"(_p) : "memory");  \
    } } while (0)
#define BARG(id) asm volatile("bar.sync %0, 128;" :: "r"(id) : "memory")

__device__ __forceinline__ void ldmx4(uint32_t* r, uint32_t addr) {
    asm volatile("ldmatrix.sync.aligned.m8n8.x4.shared.b16 {%0,%1,%2,%3}, [%4];"
        : "=r"(r[0]), "=r"(r[1]), "=r"(r[2]), "=r"(r[3]) : "r"(addr));
}
__device__ __forceinline__ void ldmx4t(uint32_t* r, uint32_t addr) {
    asm volatile("ldmatrix.sync.aligned.m8n8.x4.trans.shared.b16 {%0,%1,%2,%3}, [%4];"
        : "=r"(r[0]), "=r"(r[1]), "=r"(r[2]), "=r"(r[3]) : "r"(addr));
}
__device__ __forceinline__ void mma16816(float* d, const uint32_t* a, const uint32_t* b) {
    asm volatile("mma.sync.aligned.m16n8k16.row.col.f32.f16.f16.f32 "
        "{%0,%1,%2,%3}, {%4,%5,%6,%7}, {%8,%9}, {%0,%1,%2,%3};"
        : "+f"(d[0]), "+f"(d[1]), "+f"(d[2]), "+f"(d[3])
        : "r"(a[0]), "r"(a[1]), "r"(a[2]), "r"(a[3]), "r"(b[0]), "r"(b[1]));
}
__device__ __forceinline__ void mma16816h(uint32_t* d, const uint32_t* a, const uint32_t* b) {
    asm volatile("mma.sync.aligned.m16n8k16.row.col.f16.f16.f16.f16 "
        "{%0,%1}, {%2,%3,%4,%5}, {%6,%7}, {%0,%1};"
        : "+r"(d[0]), "+r"(d[1])
        : "r"(a[0]), "r"(a[1]), "r"(a[2]), "r"(a[3]), "r"(b[0]), "r"(b[1]));
}

__device__ __forceinline__ float sigf(float x) {
    const float c = 0.5f * 0.08838834764831845f;
    float t;
    asm("tanh.approx.f32 %0, %1;" : "=f"(t) : "f"(x * c));
    return fmaf(t, 0.5f, 0.5f);
}
__device__ __forceinline__ uint32_t packh2(float a, float b) {
    uint32_t r;
    asm("cvt.rn.f16x2.f32 %0, %1, %2;" : "=r"(r) : "f"(b), "f"(a));
    return r;
}
__device__ __forceinline__ float2 uph2(uint32_t u) {
    __half2 h = *reinterpret_cast<__half2*>(&u);
    return __half22float2(h);
}

// smem: K 32K | Q[2] 64K @32K | V[2] 64K @96K | P[2] 64K @160K | bars @224K
#define SM_K 0
#define SM_Q 32768
#define SM_V 98304
#define SM_P 163840
#define SM_BAR 229376
#define SMEM_TOTAL (229376 + 64)

__global__ __launch_bounds__(256, 1)
void sigattn_hmma(float* __restrict__ O) {
    extern __shared__ char sm[];
    const uint32_t sb = s2u(sm);
    const int tid = threadIdx.x, w = tid >> 5, lane = tid & 31;
    const int b = blockIdx.y, m0 = blockIdx.x * BM;
    const int g = lane >> 3, sx = lane & 7;
    const uint32_t bPF = sb + SM_BAR;        // P-full[2] @ +0,+8
    const uint32_t bPE = sb + SM_BAR + 16;   // P-empty[2] @ +16,+24

    if (tid == 0) {
        MBAR_INIT(bPF + 0, 128); MBAR_INIT(bPF + 8, 128);
        MBAR_INIT(bPE + 0, 128); MBAR_INIT(bPE + 8, 128);
    }

    // ---- prologue: all threads load K + Q(0) + V(0) ----
#pragma unroll
    for (int r = 0; r < 8; r++) {
        int i = tid + r * 256;
        int d = i >> 4, c = i & 15;
        uint32_t off = (uint32_t)(d * 256 + ((c ^ (d & 7)) << 4));
        CPA16(sb + SM_K + off, (const char*)g_Kh + ((size_t)(b * D_ + d) * N_ + m0 + c * 8) * 2);
        CPA16(sb + SM_Q + off, (const char*)g_Qh + ((size_t)(b * D_ + d) * N_ + c * 8) * 2);
        CPA16(sb + SM_V + off, (const char*)g_Vh + ((size_t)(b * D_ + d) * N_ + c * 8) * 2);
    }
    CPA_COMMIT();
    CPA_WAIT0();
    __syncthreads();

    if (w < 4) {
        // ================= PRODUCER: MMA1 (m32) + sigmoid -> P =================
        const int gt = tid;  // 0..127
        auto loadQ = [&](int it, int buf) {
            const int n0 = it * BN;
            const uint32_t qd = sb + SM_Q + buf * 32768;
#pragma unroll
            for (int r = 0; r < 16; r++) {
                int i = gt + r * 128;
                int d = i >> 4, c = i & 15;
                CPA16(qd + (uint32_t)(d * 256 + ((c ^ (d & 7)) << 4)),
                      (const char*)g_Qh + ((size_t)(b * D_ + d) * N_ + n0 + c * 8) * 2);
            }
        };

        // K frags for two m16 blocks (m16 index = 2w, 2w+1)
        uint32_t kf[2][8][4];
        {
            const int drow = (g >> 1) * 8 + sx;
#pragma unroll
            for (int mb = 0; mb < 2; mb++) {
                const uint32_t coff =
                    (uint32_t)((((2 * (2 * w + mb) + (g & 1)) ^ sx) & 15) << 4);
#pragma unroll
                for (int kc = 0; kc < 8; kc++)
                    ldmx4t(kf[mb][kc], sb + SM_K + (uint32_t)((kc * 16 + drow) * 256) + coff);
            }
        }

        const int qrow  = (g & 1) * 8 + sx;
        const int qcoff = g >> 1;
        const int prow0 = w * 32 + (lane >> 2);
        const int pcol0 = (lane & 3) * 2;
        int peP[2] = {0, 0};

        for (int it = 0; it < NITER; it++) {
            const int buf = it & 1;
            if (it + 1 < NITER) { loadQ(it + 1, buf ^ 1); CPA_COMMIT(); }

            const uint32_t qbuf = sb + SM_Q + buf * 32768;
            uint32_t sc[2][16][2];
#pragma unroll
            for (int mb = 0; mb < 2; mb++)
#pragma unroll
                for (int nt = 0; nt < 16; nt++) { sc[mb][nt][0] = 0u; sc[mb][nt][1] = 0u; }

#pragma unroll
            for (int kc = 0; kc < 8; kc++) {
                const uint32_t qr = qbuf + (uint32_t)((kc * 16 + qrow) * 256);
#pragma unroll
                for (int jb = 0; jb < 8; jb++) {
                    uint32_t qb[4];
                    ldmx4t(qb, qr + (uint32_t)((((2 * jb + qcoff) ^ sx) & 15) << 4));
                    mma16816h(sc[0][2 * jb],     kf[0][kc], &qb[0]);
                    mma16816h(sc[0][2 * jb + 1], kf[0][kc], &qb[2]);
                    mma16816h(sc[1][2 * jb],     kf[1][kc], &qb[0]);
                    mma16816h(sc[1][2 * jb + 1], kf[1][kc], &qb[2]);
                }
            }

            if (it >= 2) { MBAR_WAIT(bPE + 8 * buf, peP[buf]); peP[buf] ^= 1; }

            char* pd = sm + SM_P + buf * 32768;
#pragma unroll
            for (int mb = 0; mb < 2; mb++) {
                const int r0 = prow0 + mb * 16, r1 = r0 + 8;
#pragma unroll
                for (int nt = 0; nt < 16; nt++) {
                    const int n = nt * 8 + pcol0;
                    float2 f0 = uph2(sc[mb][nt][0]);
                    float2 f1 = uph2(sc[mb][nt][1]);
                    *(uint32_t*)(pd + r0 * 256 + (((nt ^ (r0 & 7)) & 15) << 4) + (n & 7) * 2)
                        = packh2(sigf(f0.x), sigf(f0.y));
                    *(uint32_t*)(pd + r1 * 256 + (((nt ^ (r1 & 7)) & 15) << 4) + (n & 7) * 2)
                        = packh2(sigf(f1.x), sigf(f1.y));
                }
            }
            MBAR_ARRIVE(bPF + 8 * buf);
            CPA_WAIT0();
            BARG(5);
        }
    } else {
        // ================= CONSUMER: MMA2 (m32) from P + V =================
        const int gt = tid - 128;  // 0..127
        auto loadV = [&](int it, int buf) {
            const int n0 = it * BN;
            const uint32_t vd = sb + SM_V + buf * 32768;
#pragma unroll
            for (int r = 0; r < 16; r++) {
                int i = gt + r * 128;
                int d = i >> 4, c = i & 15;
                CPA16(vd + (uint32_t)(d * 256 + ((c ^ (d & 7)) << 4)),
                      (const char*)g_Vh + ((size_t)(b * D_ + d) * N_ + n0 + c * 8) * 2);
            }
        };

        const int mw = w - 4;                  // 0..3
        const int rL  = sx + ((lane >> 4) << 3);
        const int cp_ = g & 1;
        float ob[2][16][4];
#pragma unroll
        for (int mb = 0; mb < 2; mb++)
#pragma unroll
            for (int jv = 0; jv < 16; jv++)
#pragma unroll
                for (int q = 0; q < 4; q++) ob[mb][jv][q] = 0.0f;
        int pfP[2] = {0, 0};

        for (int it = 0; it < NITER; it++) {
            const int buf = it & 1;
            if (it + 1 < NITER) { loadV(it + 1, buf ^ 1); CPA_COMMIT(); }

            MBAR_WAIT(bPF + 8 * buf, pfP[buf]); pfP[buf] ^= 1;

            const uint32_t pbuf = sb + SM_P + buf * 32768;
            const uint32_t vbuf = sb + SM_V + buf * 32768;
#pragma unroll
            for (int kc = 0; kc < 8; kc++) {
                uint32_t pa[2][4];
#pragma unroll
                for (int mb = 0; mb < 2; mb++) {
                    const int pr = mw * 32 + mb * 16 + (g & 1) * 8 + sx;
                    ldmx4(pa[mb], pbuf + (uint32_t)(pr * 256 +
                        ((((kc * 2 + (g >> 1)) ^ (pr & 7)) & 15) << 4)));
                }
                const uint32_t vb0 = vbuf + (uint32_t)(rL * 256) +
                    (uint32_t)((((2 * kc + cp_) ^ sx) & 15) << 4);
#pragma unroll
                for (int j = 0; j < 8; j++) {
                    uint32_t vb[4];
                    ldmx4(vb, vb0 + (uint32_t)(j * 4096));
#pragma unroll
                    for (int mb = 0; mb < 2; mb++) {
                        mma16816(ob[mb][2 * j],     pa[mb], &vb[0]);
                        mma16816(ob[mb][2 * j + 1], pa[mb], &vb[2]);
                    }
                }
            }
            MBAR_ARRIVE(bPE + 8 * buf);
            CPA_WAIT0();
            BARG(6);
        }

        // ---- epilogue ----
        float* Ob = O + (size_t)b * D_ * N_ + m0;
        const int c0 = 2 * (lane & 3);
#pragma unroll
        for (int mb = 0; mb < 2; mb++) {
            const int m = mw * 32 + mb * 16 + (lane >> 2);
#pragma unroll
            for (int jv = 0; jv < 16; jv++) {
                const int v = jv * 8 + c0;
                Ob[(size_t)v * N_ + m]           = ob[mb][jv][0];
                Ob[(size_t)(v + 1) * N_ + m]     = ob[mb][jv][1];
                Ob[(size_t)v * N_ + m + 8]       = ob[mb][jv][2];
                Ob[(size_t)(v + 1) * N_ + m + 8] = ob[mb][jv][3];
            }
        }
    }
}

// ---- preprocess: pure fp32 -> fp16 cast, native layouts ----
__global__ void prep_cast(const float* __restrict__ Q, const float* __restrict__ K,
                          const float* __restrict__ V) {
    int i = blockIdx.x * 256 + threadIdx.x;
    const float* src = (blockIdx.y == 0) ? Q : (blockIdx.y == 1) ? K : V;
    __half* dst = (blockIdx.y == 0) ? g_Qh : (blockIdx.y == 1) ? g_Kh : g_Vh;
    float4 v = ((const float4*)src)[i];
    __half2* o = (__half2*)dst;
    o[2 * i]     = __floats2half2_rn(v.x, v.y);
    o[2 * i + 1] = __floats2half2_rn(v.z, v.w);
}

extern "C" void kernel_launch(void* const* d_in, const int* in_sizes, int n_in,
                              void* d_out, int out_size) {
    const float* Q = (const float*)d_in[0];
    const float* K = (const float*)d_in[1];
    const float* V = (const float*)d_in[2];
    float* O = (float*)d_out;

    prep_cast<<<dim3((B_ * D_ * N_ / 4) / 256, 3), 256>>>(Q, K, V);

    cudaFuncSetAttribute(sigattn_hmma, cudaFuncAttributeMaxDynamicSharedMemorySize, SMEM_TOTAL);
    sigattn_hmma<<<dim3(N_ / BM, B_), 256, SMEM_TOTAL>>>(O);
}